// round 12
// baseline (speedup 1.0000x reference)
#include <cuda_runtime.h>
#include <cuda_bf16.h>
#include <mma.h>
#include <cstdint>
using namespace nvcuda;

// ---------------------------------------------------------------------------
// Problem constants
// ---------------------------------------------------------------------------
#define LQ 4096
#define NBATCH 4
#define EM 1024
#define NH 16
#define HD 64
#define MROWS (LQ * NBATCH)        // 16384
#define NCOLS (NBATCH * EM)        // 4096 ([L, N*E] view)
#define KSPLIT 2048                // hi|lo stored side by side
#define NROWBLK 32

// ---------------------------------------------------------------------------
// Scratch (device globals; allocation is forbidden)
// ---------------------------------------------------------------------------
__device__ __nv_bfloat16 g_Aw[(size_t)MROWS * KSPLIT];    // 64MB, reused per GEMM
__device__ __nv_bfloat16 g_Wq[(size_t)EM * KSPLIT];
__device__ __nv_bfloat16 g_Wk[(size_t)EM * KSPLIT];
__device__ __nv_bfloat16 g_Wv[(size_t)EM * KSPLIT];
__device__ __nv_bfloat16 g_Wo[(size_t)EM * KSPLIT];
__device__ float g_Qp[(size_t)MROWS * EM];
__device__ float g_Kp[(size_t)MROWS * EM];
__device__ float g_Vp[(size_t)MROWS * EM];
__device__ unsigned int g_cmax[NCOLS];
__device__ float g_csum[NCOLS];
__device__ float g_psum[NROWBLK * NCOLS];
__device__ float g_vpr8[8 * NBATCH * NH * HD * HD];       // L-split partials
__device__ float g_vpr[NBATCH * NH * HD * HD];            // [nh][d][e']

__device__ __forceinline__ uint32_t smem_to_u32(const void* p) {
    uint32_t a;
    asm("{ .reg .u64 t; cvta.to.shared.u64 t, %1; cvt.u32.u64 %0, t; }"
        : "=r"(a) : "l"(p));
    return a;
}

__device__ __forceinline__ void cp16(uint32_t sp, const void* gp) {
    asm volatile("cp.async.cg.shared.global [%0], [%1], 16;"
                 :: "r"(sp), "l"(gp));
}
#define CP_COMMIT() asm volatile("cp.async.commit_group;" ::: "memory")
#define CP_WAIT1()  asm volatile("cp.async.wait_group 1;" ::: "memory")
#define CP_WAIT0()  asm volatile("cp.async.wait_group 0;" ::: "memory")

// ---------------------------------------------------------------------------
// Split-bf16 NT GEMM with 3-phase error correction:
//   C = Ah*Bh^T + Al*Bh^T + Ah*Bl^T   (fp32 accumulate)
// A,B stored as [rows, 2048] = [hi(1024) | lo(1024)].
// CTA tile 128x256, warp tile 64x64 (8 warps, 2x4), BK=32,
// 3-stage cp.async pipeline, one __syncthreads per iteration.
// Tail: wait_group 0 once no further groups are committed (stage GITER-1
// must be fully landed before iter GITER-1 computes it).
// ---------------------------------------------------------------------------
#define BM 128
#define BN 256
#define BK 32
#define LDSM 40                    // bf16 leading dim (pad 32 -> 40)
#define PHITER (1024 / BK)         // 32 iterations per phase
#define GITER (3 * PHITER)         // 96
#define SA_STAGE (BM * LDSM)       // 5120 bf16
#define SB_STAGE (BN * LDSM)       // 10240 bf16
#define STAGE_ELE (SA_STAGE + SB_STAGE)
#define GEMM_SMEM (3 * STAGE_ELE * 2)   // 92160 bytes

__global__ __launch_bounds__(256, 1) void gemm_bf16(
    const __nv_bfloat16* __restrict__ A,
    const __nv_bfloat16* __restrict__ B,
    float* __restrict__ C)
{
    extern __shared__ __nv_bfloat16 smem[];
    __nv_bfloat16* sA[3];
    __nv_bfloat16* sB[3];
    #pragma unroll
    for (int s = 0; s < 3; s++) {
        sA[s] = smem + s * STAGE_ELE;
        sB[s] = sA[s] + SA_STAGE;
    }

    int tid = threadIdx.x;
    int m0 = blockIdx.y * BM, n0 = blockIdx.x * BN;
    int wid = tid >> 5;
    int wm = wid >> 2;               // 0..1  -> 64 rows
    int wn = wid & 3;                // 0..3  -> 64 cols

    wmma::fragment<wmma::accumulator, 16, 16, 16, float> acc[4][4];
    #pragma unroll
    for (int i = 0; i < 4; i++)
        #pragma unroll
        for (int j = 0; j < 4; j++)
            wmma::fill_fragment(acc[i][j], 0.0f);

    // logical iter -> (A offset, B offset) for 3-phase split
    #define AOFF(it) ((((it) >> 5) == 1 ? 1024 : 0) + ((it) & 31) * BK)
    #define BOFF(it) ((((it) >> 5) == 2 ? 1024 : 0) + ((it) & 31) * BK)

    #define LOAD_STAGE(s, ka, kb) do { \
        _Pragma("unroll") \
        for (int t = 0; t < 2; t++) { \
            int idx = tid + t * 256;          /* 0..511 */ \
            int r = idx >> 2, c8 = (idx & 3) * 8; \
            cp16(smem_to_u32(&sA[s][r * LDSM + c8]), \
                 A + (size_t)(m0 + r) * KSPLIT + (ka) + c8); \
        } \
        _Pragma("unroll") \
        for (int t = 0; t < 4; t++) { \
            int idx = tid + t * 256;          /* 0..1023 */ \
            int r = idx >> 2, c8 = (idx & 3) * 8; \
            cp16(smem_to_u32(&sB[s][r * LDSM + c8]), \
                 B + (size_t)(n0 + r) * KSPLIT + (kb) + c8); \
        } \
        CP_COMMIT(); \
    } while (0)

    // Prologue: stages 0,1 in flight
    LOAD_STAGE(0, AOFF(0), BOFF(0));
    LOAD_STAGE(1, AOFF(1), BOFF(1));
    CP_WAIT1();              // stage 0 complete (<=1 group outstanding)
    __syncthreads();

    for (int it = 0; it < GITER; it++) {
        bool prefetch = (it + 2 < GITER);
        if (prefetch) {
            int nx = it + 2;
            LOAD_STAGE(nx % 3, AOFF(nx), BOFF(nx));
        }

        const __nv_bfloat16* pa = sA[it % 3];
        const __nv_bfloat16* pb = sB[it % 3];
        #pragma unroll
        for (int kk = 0; kk < BK; kk += 16) {
            wmma::fragment<wmma::matrix_a, 16, 16, 16, __nv_bfloat16,
                           wmma::row_major> af[4];
            #pragma unroll
            for (int i = 0; i < 4; i++)
                wmma::load_matrix_sync(af[i],
                    pa + (wm * 64 + i * 16) * LDSM + kk, LDSM);
            #pragma unroll
            for (int j = 0; j < 4; j++) {
                wmma::fragment<wmma::matrix_b, 16, 16, 16, __nv_bfloat16,
                               wmma::col_major> bf;
                wmma::load_matrix_sync(bf,
                    pb + (wn * 64 + j * 16) * LDSM + kk, LDSM);
                #pragma unroll
                for (int i = 0; i < 4; i++)
                    wmma::mma_sync(acc[i][j], af[i], bf, acc[i][j]);
            }
        }

        // Ensure stage it+1 is fully landed before next iteration reads it.
        // While prefetching, the newest group is stage it+2 -> wait_group 1.
        // Once prefetch stops, the newest group IS stage GITER-1 -> wait 0.
        if (prefetch) CP_WAIT1(); else CP_WAIT0();
        __syncthreads();     // all warps done reading stage it before the
                             // next iteration's load overwrites it (s (it+3)%3)
    }

    #pragma unroll
    for (int i = 0; i < 4; i++)
        #pragma unroll
        for (int j = 0; j < 4; j++) {
            int row0 = m0 + wm * 64 + i * 16;
            int col0 = n0 + wn * 64 + j * 16;
            wmma::store_matrix_sync(C + (size_t)row0 * EM + col0, acc[i][j],
                                    EM, wmma::mem_row_major);
        }
    #undef LOAD_STAGE
    #undef AOFF
    #undef BOFF
}

// ---------------------------------------------------------------------------
// fp32 -> bf16 hi|lo split: src[rows,1024] -> dst[rows,2048] (hi | lo)
// ---------------------------------------------------------------------------
__global__ void split_mat(const float* __restrict__ src,
                          __nv_bfloat16* __restrict__ dst, int total4)
{
    for (int i4 = blockIdx.x * blockDim.x + threadIdx.x; i4 < total4;
         i4 += gridDim.x * blockDim.x) {
        int i = i4 << 2;
        float4 f = ((const float4*)src)[i4];
        int r = i >> 10, c = i & 1023;
        size_t o = ((size_t)r << 11) + c;
        float fv[4] = {f.x, f.y, f.z, f.w};
        __nv_bfloat162 h0, h1, l0, l1;
        __nv_bfloat16 h[4], l[4];
        #pragma unroll
        for (int j = 0; j < 4; j++) {
            h[j] = __float2bfloat16(fv[j]);
            l[j] = __float2bfloat16(fv[j] - __bfloat162float(h[j]));
        }
        h0.x = h[0]; h0.y = h[1]; h1.x = h[2]; h1.y = h[3];
        l0.x = l[0]; l0.y = l[1]; l1.x = l[2]; l1.y = l[3];
        *(__nv_bfloat162*)(dst + o)        = h0;
        *(__nv_bfloat162*)(dst + o + 2)    = h1;
        *(__nv_bfloat162*)(dst + o + 1024) = l0;
        *(__nv_bfloat162*)(dst + o + 1026) = l1;
    }
}

// ---------------------------------------------------------------------------
// Bias add (final output only; bk cancels in softmax_l, bq/bv folded later)
// ---------------------------------------------------------------------------
__global__ void add_bias(float* __restrict__ C, const float* __restrict__ b,
                         int total)
{
    for (int i = blockIdx.x * blockDim.x + threadIdx.x; i < total;
         i += gridDim.x * blockDim.x)
        C[i] += __ldg(&b[i & (EM - 1)]);
}

// ---------------------------------------------------------------------------
// Column softmax stats (over l, per (n,e) column of Kp; bias-free — it cancels)
// ---------------------------------------------------------------------------
__device__ __forceinline__ unsigned int fenc(float f) {
    unsigned int u = __float_as_uint(f);
    return (u & 0x80000000u) ? ~u : (u | 0x80000000u);
}
__device__ __forceinline__ float fdec(unsigned int u) {
    return (u & 0x80000000u) ? __uint_as_float(u & 0x7fffffffu)
                             : __uint_as_float(~u);
}

__global__ void init_stats()
{
    int c = blockIdx.x * blockDim.x + threadIdx.x;
    if (c < NCOLS) g_cmax[c] = 0u;
}

__global__ void col_max_k(const float* __restrict__ Kp)
{
    int c = blockIdx.x * blockDim.x + threadIdx.x;
    int r0 = blockIdx.y * (LQ / NROWBLK);
    float m = -3.0e38f;
    #pragma unroll 4
    for (int r = 0; r < LQ / NROWBLK; r++)
        m = fmaxf(m, Kp[(size_t)(r0 + r) * NCOLS + c]);
    atomicMax(&g_cmax[c], fenc(m));
}

__global__ void col_sum_k(const float* __restrict__ Kp)
{
    int c = blockIdx.x * blockDim.x + threadIdx.x;
    int rb = blockIdx.y;
    int r0 = rb * (LQ / NROWBLK);
    float mx = fdec(g_cmax[c]);
    float s = 0.0f;
    #pragma unroll 4
    for (int r = 0; r < LQ / NROWBLK; r++)
        s += __expf(Kp[(size_t)(r0 + r) * NCOLS + c] - mx);
    g_psum[rb * NCOLS + c] = s;
}

__global__ void sum_combine()
{
    int c = blockIdx.x * blockDim.x + threadIdx.x;
    if (c >= NCOLS) return;
    float s = 0.0f;
    #pragma unroll
    for (int rb = 0; rb < NROWBLK; rb++) s += g_psum[rb * NCOLS + c];
    g_csum[c] = s;
}

// ---------------------------------------------------------------------------
// v' = softmax_l(K)^T @ V per (n,h); L split into 8 partials
// ---------------------------------------------------------------------------
__global__ __launch_bounds__(256) void vprime_k(const float* __restrict__ Kp,
                                                const float* __restrict__ Vp)
{
    int nh = blockIdx.x;
    int ls = blockIdx.y;                // 0..7
    int n = nh >> 4, h = nh & 15;
    int cbase = n * EM + h * HD;

    __shared__ float sK[32][64];
    __shared__ float sV[32][64];
    __shared__ float sMax[64], sInv[64];

    int tid = threadIdx.x;
    if (tid < 64) {
        sMax[tid] = fdec(g_cmax[cbase + tid]);
        sInv[tid] = 1.0f / g_csum[cbase + tid];
    }
    __syncthreads();

    float accv[16];
    #pragma unroll
    for (int i = 0; i < 16; i++) accv[i] = 0.0f;
    int tx = tid & 63;
    int ty = tid >> 6;

    int lbeg = ls * (LQ / 8), lend = lbeg + (LQ / 8);
    for (int l0 = lbeg; l0 < lend; l0 += 32) {
        #pragma unroll
        for (int t = 0; t < 8; t++) {
            int idx = tid + t * 256;
            int r = idx >> 6, cc = idx & 63;
            size_t g = (size_t)(l0 + r) * NCOLS + cbase + cc;
            float kv = Kp[g];
            sK[r][cc] = __expf(kv - sMax[cc]) * sInv[cc];
            sV[r][cc] = Vp[g];
        }
        __syncthreads();
        #pragma unroll 8
        for (int l = 0; l < 32; l++) {
            float vv = sV[l][tx];
            #pragma unroll
            for (int i = 0; i < 16; i++)
                accv[i] += sK[l][ty + i * 4] * vv;
        }
        __syncthreads();
    }
    #pragma unroll
    for (int i = 0; i < 16; i++)
        g_vpr8[((size_t)ls * 64 + nh) * (HD * HD) + (ty + i * 4) * HD + tx] = accv[i];
}

// combine partials; fold bv: v'[d][e'] += bv[h*HD + e'] (since sum_l softmax = 1)
__global__ void vpr_combine(const float* __restrict__ bv)
{
    int nh = blockIdx.x;
    int hb = (nh & 15) * HD;
    for (int idx = threadIdx.x; idx < HD * HD; idx += blockDim.x) {
        float s = 0.0f;
        #pragma unroll
        for (int ls = 0; ls < 8; ls++)
            s += g_vpr8[((size_t)ls * 64 + nh) * (HD * HD) + idx];
        g_vpr[nh * (HD * HD) + idx] = s + __ldg(&bv[hb + (idx & 63)]);
    }
}

// ---------------------------------------------------------------------------
// attn = softmax_d(Q + bq) @ v'; writes hi|lo bf16 directly into g_Aw
// ---------------------------------------------------------------------------
__global__ __launch_bounds__(256) void attn_k(const float* __restrict__ Qp,
                                              const float* __restrict__ bq)
{
    int nh = blockIdx.x;
    int n = nh >> 4, h = nh & 15;
    int cbase = n * EM + h * HD;
    int hb = h * HD;

    __shared__ float sU[64][64];
    int tid = threadIdx.x;
    #pragma unroll
    for (int t = 0; t < 16; t++) {
        int idx = tid + t * 256;
        sU[idx >> 6][idx & 63] = g_vpr[nh * (HD * HD) + idx];
    }
    __syncthreads();

    int wid = tid >> 5, lane = tid & 31;
    float b0 = __ldg(&bq[hb + lane]);
    float b1 = __ldg(&bq[hb + lane + 32]);
    for (int lw = 0; lw < 16; lw++) {
        int l = blockIdx.y * 128 + wid * 16 + lw;
        size_t rb = (size_t)l * NCOLS + cbase;
        float q0 = Qp[rb + lane] + b0;
        float q1 = Qp[rb + lane + 32] + b1;
        float m = fmaxf(q0, q1);
        #pragma unroll
        for (int off = 16; off > 0; off >>= 1)
            m = fmaxf(m, __shfl_xor_sync(0xffffffffu, m, off));
        float e0 = __expf(q0 - m), e1 = __expf(q1 - m);
        float s = e0 + e1;
        #pragma unroll
        for (int off = 16; off > 0; off >>= 1)
            s += __shfl_xor_sync(0xffffffffu, s, off);
        float inv = 1.0f / s;
        e0 *= inv; e1 *= inv;
        float a0 = 0.0f, a1 = 0.0f;
        #pragma unroll
        for (int src = 0; src < 32; src++) {
            float p = __shfl_sync(0xffffffffu, e0, src);
            float qv = __shfl_sync(0xffffffffu, e1, src);
            a0 += p * sU[src][lane]      + qv * sU[src + 32][lane];
            a1 += p * sU[src][lane + 32] + qv * sU[src + 32][lane + 32];
        }
        size_t ob = ((size_t)l * NBATCH + n) * KSPLIT + h * HD;
        __nv_bfloat16 h0 = __float2bfloat16(a0);
        __nv_bfloat16 l0b = __float2bfloat16(a0 - __bfloat162float(h0));
        __nv_bfloat16 h1 = __float2bfloat16(a1);
        __nv_bfloat16 l1b = __float2bfloat16(a1 - __bfloat162float(h1));
        g_Aw[ob + lane] = h0;
        g_Aw[ob + lane + 32] = h1;
        g_Aw[ob + 1024 + lane] = l0b;
        g_Aw[ob + 1024 + lane + 32] = l1b;
    }
}

// ---------------------------------------------------------------------------
// Launch
// ---------------------------------------------------------------------------
extern "C" void kernel_launch(void* const* d_in, const int* in_sizes, int n_in,
                              void* d_out, int out_size)
{
    (void)in_sizes; (void)n_in; (void)out_size;
    const float* q  = (const float*)d_in[0];
    const float* k  = (const float*)d_in[1];
    const float* v  = (const float*)d_in[2];
    const float* Wq = (const float*)d_in[3];
    const float* bq = (const float*)d_in[4];
    const float* Wk = (const float*)d_in[5];
    const float* Wv = (const float*)d_in[7];
    const float* bv = (const float*)d_in[8];
    const float* Wo = (const float*)d_in[9];
    const float* bo = (const float*)d_in[10];
    float* out = (float*)d_out;

    void *pAw, *pWq, *pWk, *pWv, *pWo, *pQp, *pKp, *pVp;
    cudaGetSymbolAddress(&pAw, g_Aw);
    cudaGetSymbolAddress(&pWq, g_Wq);
    cudaGetSymbolAddress(&pWk, g_Wk);
    cudaGetSymbolAddress(&pWv, g_Wv);
    cudaGetSymbolAddress(&pWo, g_Wo);
    cudaGetSymbolAddress(&pQp, g_Qp);
    cudaGetSymbolAddress(&pKp, g_Kp);
    cudaGetSymbolAddress(&pVp, g_Vp);

    cudaFuncSetAttribute(gemm_bf16,
                         cudaFuncAttributeMaxDynamicSharedMemorySize, GEMM_SMEM);

    dim3 ggrid(EM / BN, MROWS / BM);   // (4, 128)
    const int ACT4 = MROWS * EM / 4;
    const int W4 = EM * EM / 4;
    const int TOT = MROWS * EM;

    // weight splits
    split_mat<<<512, 256>>>(Wq, (__nv_bfloat16*)pWq, W4);
    split_mat<<<512, 256>>>(Wk, (__nv_bfloat16*)pWk, W4);
    split_mat<<<512, 256>>>(Wv, (__nv_bfloat16*)pWv, W4);
    split_mat<<<512, 256>>>(Wo, (__nv_bfloat16*)pWo, W4);

    // projections (bias-free: bk cancels, bq/bv folded downstream)
    split_mat<<<4096, 256>>>(q, (__nv_bfloat16*)pAw, ACT4);
    gemm_bf16<<<ggrid, 256, GEMM_SMEM>>>((const __nv_bfloat16*)pAw,
                              (const __nv_bfloat16*)pWq, (float*)pQp);
    split_mat<<<4096, 256>>>(k, (__nv_bfloat16*)pAw, ACT4);
    gemm_bf16<<<ggrid, 256, GEMM_SMEM>>>((const __nv_bfloat16*)pAw,
                              (const __nv_bfloat16*)pWk, (float*)pKp);
    split_mat<<<4096, 256>>>(v, (__nv_bfloat16*)pAw, ACT4);
    gemm_bf16<<<ggrid, 256, GEMM_SMEM>>>((const __nv_bfloat16*)pAw,
                              (const __nv_bfloat16*)pWv, (float*)pVp);

    // column softmax stats over l for K
    init_stats<<<16, 256>>>();
    col_max_k<<<dim3(16, NROWBLK), 256>>>((const float*)pKp);
    col_sum_k<<<dim3(16, NROWBLK), 256>>>((const float*)pKp);
    sum_combine<<<16, 256>>>();

    // attention core
    vprime_k<<<dim3(NBATCH * NH, 8), 256>>>((const float*)pKp, (const float*)pVp);
    vpr_combine<<<NBATCH * NH, 256>>>(bv);
    attn_k<<<dim3(NBATCH * NH, 32), 256>>>((const float*)pQp, bq);

    // output projection (+bo)
    gemm_bf16<<<ggrid, 256, GEMM_SMEM>>>((const __nv_bfloat16*)pAw,
                              (const __nv_bfloat16*)pWo, out);
    add_bias<<<2048, 256>>>(out, bo, TOT);
}

// round 15
// speedup vs baseline: 1.1093x; 1.1093x over previous
#include <cuda_runtime.h>
#include <cuda_bf16.h>
#include <mma.h>
#include <cstdint>
using namespace nvcuda;

// ---------------------------------------------------------------------------
// Problem constants
// ---------------------------------------------------------------------------
#define LQ 4096
#define NBATCH 4
#define EM 1024
#define NH 16
#define HD 64
#define MROWS (LQ * NBATCH)        // 16384
#define NCOLS (NBATCH * EM)        // 4096 ([L, N*E] view)
#define KSPLIT 2048                // hi|lo stored side by side
#define NROWBLK 32

// ---------------------------------------------------------------------------
// Scratch (device globals; allocation is forbidden)
// ---------------------------------------------------------------------------
__device__ __nv_bfloat16 g_Aw[(size_t)MROWS * KSPLIT];    // 64MB, reused per GEMM
__device__ __nv_bfloat16 g_Wq[(size_t)EM * KSPLIT];
__device__ __nv_bfloat16 g_Wk[(size_t)EM * KSPLIT];
__device__ __nv_bfloat16 g_Wv[(size_t)EM * KSPLIT];
__device__ __nv_bfloat16 g_Wo[(size_t)EM * KSPLIT];
__device__ float g_Qp[(size_t)MROWS * EM];
__device__ float g_Kp[(size_t)MROWS * EM];
__device__ float g_Vp[(size_t)MROWS * EM];
__device__ unsigned int g_cmax[NCOLS];
__device__ float g_csum[NCOLS];
__device__ float g_psum[NROWBLK * NCOLS];
__device__ float g_vpr8[8 * NBATCH * NH * HD * HD];       // L-split partials
__device__ float g_vpr[NBATCH * NH * HD * HD];            // [nh][d][e']

__device__ __forceinline__ uint32_t smem_to_u32(const void* p) {
    uint32_t a;
    asm("{ .reg .u64 t; cvta.to.shared.u64 t, %1; cvt.u32.u64 %0, t; }"
        : "=r"(a) : "l"(p));
    return a;
}

__device__ __forceinline__ void cp16(uint32_t sp, const void* gp) {
    asm volatile("cp.async.cg.shared.global [%0], [%1], 16;"
                 :: "r"(sp), "l"(gp));
}
#define CP_COMMIT() asm volatile("cp.async.commit_group;" ::: "memory")
#define CP_WAIT1()  asm volatile("cp.async.wait_group 1;" ::: "memory")
#define CP_WAIT0()  asm volatile("cp.async.wait_group 0;" ::: "memory")

// ---------------------------------------------------------------------------
// Split-bf16 NT GEMM with 3-phase error correction:
//   C = Ah*Bh^T + Al*Bh^T + Ah*Bl^T   (fp32 accumulate)
// A,B stored as [rows, 2048] = [hi(1024) | lo(1024)].
// R10 proven shape: CTA tile 128x128, 8 warps (warp tile 32x64), BK=32,
// occupancy 2. Upgrade vs R10: 3-stage cp.async pipeline with ONE
// __syncthreads per iteration (was 2-stage with two barriers).
// Tail: wait_group 0 once no further groups are committed.
// ---------------------------------------------------------------------------
#define BM 128
#define BN 128
#define BK 32
#define LDSM 40                    // bf16 leading dim (pad 32 -> 40)
#define PHITER (1024 / BK)         // 32 iterations per phase
#define GITER (3 * PHITER)         // 96
#define SA_STAGE (BM * LDSM)       // 5120 bf16
#define SB_STAGE (BN * LDSM)       // 5120 bf16
#define STAGE_ELE (SA_STAGE + SB_STAGE)
#define GEMM_SMEM (3 * STAGE_ELE * 2)   // 61440 bytes

__global__ __launch_bounds__(256, 2) void gemm_bf16(
    const __nv_bfloat16* __restrict__ A,
    const __nv_bfloat16* __restrict__ B,
    float* __restrict__ C)
{
    extern __shared__ __nv_bfloat16 smem[];
    __nv_bfloat16* sA[3];
    __nv_bfloat16* sB[3];
    #pragma unroll
    for (int s = 0; s < 3; s++) {
        sA[s] = smem + s * STAGE_ELE;
        sB[s] = sA[s] + SA_STAGE;
    }

    int tid = threadIdx.x;
    int m0 = blockIdx.y * BM, n0 = blockIdx.x * BN;
    int wid = tid >> 5;
    int wm = wid & 3;                // 4 warp rows -> 32 rows each
    int wn = wid >> 2;               // 2 warp cols -> 64 cols each

    wmma::fragment<wmma::accumulator, 16, 16, 16, float> acc[2][4];
    #pragma unroll
    for (int i = 0; i < 2; i++)
        #pragma unroll
        for (int j = 0; j < 4; j++)
            wmma::fill_fragment(acc[i][j], 0.0f);

    // logical iter -> (A offset, B offset) for 3-phase split
    #define AOFF(it) ((((it) >> 5) == 1 ? 1024 : 0) + ((it) & 31) * BK)
    #define BOFF(it) ((((it) >> 5) == 2 ? 1024 : 0) + ((it) & 31) * BK)

    // 128 rows x 32 cols = 512 16B-chunks per matrix; 2 per thread.
    #define LOAD_STAGE(s, ka, kb) do { \
        _Pragma("unroll") \
        for (int t = 0; t < 2; t++) { \
            int idx = tid + t * 256;          /* 0..511 */ \
            int r = idx >> 2, c8 = (idx & 3) * 8; \
            cp16(smem_to_u32(&sA[s][r * LDSM + c8]), \
                 A + (size_t)(m0 + r) * KSPLIT + (ka) + c8); \
        } \
        _Pragma("unroll") \
        for (int t = 0; t < 2; t++) { \
            int idx = tid + t * 256; \
            int r = idx >> 2, c8 = (idx & 3) * 8; \
            cp16(smem_to_u32(&sB[s][r * LDSM + c8]), \
                 B + (size_t)(n0 + r) * KSPLIT + (kb) + c8); \
        } \
        CP_COMMIT(); \
    } while (0)

    // Prologue: stages 0,1 in flight
    LOAD_STAGE(0, AOFF(0), BOFF(0));
    LOAD_STAGE(1, AOFF(1), BOFF(1));
    CP_WAIT1();              // stage 0 complete (<=1 group outstanding)
    __syncthreads();

    for (int it = 0; it < GITER; it++) {
        bool prefetch = (it + 2 < GITER);
        if (prefetch) {
            int nx = it + 2;
            LOAD_STAGE(nx % 3, AOFF(nx), BOFF(nx));
        }

        const __nv_bfloat16* pa = sA[it % 3];
        const __nv_bfloat16* pb = sB[it % 3];
        #pragma unroll
        for (int kk = 0; kk < BK; kk += 16) {
            wmma::fragment<wmma::matrix_a, 16, 16, 16, __nv_bfloat16,
                           wmma::row_major> af[2];
            wmma::load_matrix_sync(af[0], pa + (wm * 32) * LDSM + kk, LDSM);
            wmma::load_matrix_sync(af[1], pa + (wm * 32 + 16) * LDSM + kk, LDSM);
            #pragma unroll
            for (int j = 0; j < 4; j++) {
                wmma::fragment<wmma::matrix_b, 16, 16, 16, __nv_bfloat16,
                               wmma::col_major> bf;
                wmma::load_matrix_sync(bf,
                    pb + (wn * 64 + j * 16) * LDSM + kk, LDSM);
                wmma::mma_sync(acc[0][j], af[0], bf, acc[0][j]);
                wmma::mma_sync(acc[1][j], af[1], bf, acc[1][j]);
            }
        }

        // Stage it+1 must be landed before the next iteration reads it.
        // While prefetching, the newest group is stage it+2 -> wait_group 1.
        // Once prefetch stops, the newest group IS stage GITER-1 -> wait 0.
        if (prefetch) CP_WAIT1(); else CP_WAIT0();
        __syncthreads();     // all warps done reading stage it before the
                             // next iteration's load overwrites stage (it+3)%3
    }

    #pragma unroll
    for (int i = 0; i < 2; i++)
        #pragma unroll
        for (int j = 0; j < 4; j++) {
            int row0 = m0 + wm * 32 + i * 16;
            int col0 = n0 + wn * 64 + j * 16;
            wmma::store_matrix_sync(C + (size_t)row0 * EM + col0, acc[i][j],
                                    EM, wmma::mem_row_major);
        }
    #undef LOAD_STAGE
    #undef AOFF
    #undef BOFF
}

// ---------------------------------------------------------------------------
// fp32 -> bf16 hi|lo split: src[rows,1024] -> dst[rows,2048] (hi | lo)
// ---------------------------------------------------------------------------
__global__ void split_mat(const float* __restrict__ src,
                          __nv_bfloat16* __restrict__ dst, int total4)
{
    for (int i4 = blockIdx.x * blockDim.x + threadIdx.x; i4 < total4;
         i4 += gridDim.x * blockDim.x) {
        int i = i4 << 2;
        float4 f = ((const float4*)src)[i4];
        int r = i >> 10, c = i & 1023;
        size_t o = ((size_t)r << 11) + c;
        float fv[4] = {f.x, f.y, f.z, f.w};
        __nv_bfloat162 h0, h1, l0, l1;
        __nv_bfloat16 h[4], l[4];
        #pragma unroll
        for (int j = 0; j < 4; j++) {
            h[j] = __float2bfloat16(fv[j]);
            l[j] = __float2bfloat16(fv[j] - __bfloat162float(h[j]));
        }
        h0.x = h[0]; h0.y = h[1]; h1.x = h[2]; h1.y = h[3];
        l0.x = l[0]; l0.y = l[1]; l1.x = l[2]; l1.y = l[3];
        *(__nv_bfloat162*)(dst + o)        = h0;
        *(__nv_bfloat162*)(dst + o + 2)    = h1;
        *(__nv_bfloat162*)(dst + o + 1024) = l0;
        *(__nv_bfloat162*)(dst + o + 1026) = l1;
    }
}

// ---------------------------------------------------------------------------
// Bias add (final output only; bk cancels in softmax_l, bq/bv folded later)
// ---------------------------------------------------------------------------
__global__ void add_bias(float* __restrict__ C, const float* __restrict__ b,
                         int total)
{
    for (int i = blockIdx.x * blockDim.x + threadIdx.x; i < total;
         i += gridDim.x * blockDim.x)
        C[i] += __ldg(&b[i & (EM - 1)]);
}

// ---------------------------------------------------------------------------
// Column softmax stats (over l, per (n,e) column of Kp; bias-free — it cancels)
// ---------------------------------------------------------------------------
__device__ __forceinline__ unsigned int fenc(float f) {
    unsigned int u = __float_as_uint(f);
    return (u & 0x80000000u) ? ~u : (u | 0x80000000u);
}
__device__ __forceinline__ float fdec(unsigned int u) {
    return (u & 0x80000000u) ? __uint_as_float(u & 0x7fffffffu)
                             : __uint_as_float(~u);
}

__global__ void init_stats()
{
    int c = blockIdx.x * blockDim.x + threadIdx.x;
    if (c < NCOLS) g_cmax[c] = 0u;
}

__global__ void col_max_k(const float* __restrict__ Kp)
{
    int c = blockIdx.x * blockDim.x + threadIdx.x;
    int r0 = blockIdx.y * (LQ / NROWBLK);
    float m = -3.0e38f;
    #pragma unroll 4
    for (int r = 0; r < LQ / NROWBLK; r++)
        m = fmaxf(m, Kp[(size_t)(r0 + r) * NCOLS + c]);
    atomicMax(&g_cmax[c], fenc(m));
}

__global__ void col_sum_k(const float* __restrict__ Kp)
{
    int c = blockIdx.x * blockDim.x + threadIdx.x;
    int rb = blockIdx.y;
    int r0 = rb * (LQ / NROWBLK);
    float mx = fdec(g_cmax[c]);
    float s = 0.0f;
    #pragma unroll 4
    for (int r = 0; r < LQ / NROWBLK; r++)
        s += __expf(Kp[(size_t)(r0 + r) * NCOLS + c] - mx);
    g_psum[rb * NCOLS + c] = s;
}

__global__ void sum_combine()
{
    int c = blockIdx.x * blockDim.x + threadIdx.x;
    if (c >= NCOLS) return;
    float s = 0.0f;
    #pragma unroll
    for (int rb = 0; rb < NROWBLK; rb++) s += g_psum[rb * NCOLS + c];
    g_csum[c] = s;
}

// ---------------------------------------------------------------------------
// v' = softmax_l(K)^T @ V per (n,h); L split into 8 partials
// ---------------------------------------------------------------------------
__global__ __launch_bounds__(256) void vprime_k(const float* __restrict__ Kp,
                                                const float* __restrict__ Vp)
{
    int nh = blockIdx.x;
    int ls = blockIdx.y;                // 0..7
    int n = nh >> 4, h = nh & 15;
    int cbase = n * EM + h * HD;

    __shared__ float sK[32][64];
    __shared__ float sV[32][64];
    __shared__ float sMax[64], sInv[64];

    int tid = threadIdx.x;
    if (tid < 64) {
        sMax[tid] = fdec(g_cmax[cbase + tid]);
        sInv[tid] = 1.0f / g_csum[cbase + tid];
    }
    __syncthreads();

    float accv[16];
    #pragma unroll
    for (int i = 0; i < 16; i++) accv[i] = 0.0f;
    int tx = tid & 63;
    int ty = tid >> 6;

    int lbeg = ls * (LQ / 8), lend = lbeg + (LQ / 8);
    for (int l0 = lbeg; l0 < lend; l0 += 32) {
        #pragma unroll
        for (int t = 0; t < 8; t++) {
            int idx = tid + t * 256;
            int r = idx >> 6, cc = idx & 63;
            size_t g = (size_t)(l0 + r) * NCOLS + cbase + cc;
            float kv = Kp[g];
            sK[r][cc] = __expf(kv - sMax[cc]) * sInv[cc];
            sV[r][cc] = Vp[g];
        }
        __syncthreads();
        #pragma unroll 8
        for (int l = 0; l < 32; l++) {
            float vv = sV[l][tx];
            #pragma unroll
            for (int i = 0; i < 16; i++)
                accv[i] += sK[l][ty + i * 4] * vv;
        }
        __syncthreads();
    }
    #pragma unroll
    for (int i = 0; i < 16; i++)
        g_vpr8[((size_t)ls * 64 + nh) * (HD * HD) + (ty + i * 4) * HD + tx] = accv[i];
}

// combine partials; fold bv: v'[d][e'] += bv[h*HD + e'] (since sum_l softmax = 1)
__global__ void vpr_combine(const float* __restrict__ bv)
{
    int nh = blockIdx.x;
    int hb = (nh & 15) * HD;
    for (int idx = threadIdx.x; idx < HD * HD; idx += blockDim.x) {
        float s = 0.0f;
        #pragma unroll
        for (int ls = 0; ls < 8; ls++)
            s += g_vpr8[((size_t)ls * 64 + nh) * (HD * HD) + idx];
        g_vpr[nh * (HD * HD) + idx] = s + __ldg(&bv[hb + (idx & 63)]);
    }
}

// ---------------------------------------------------------------------------
// attn = softmax_d(Q + bq) @ v'; writes hi|lo bf16 directly into g_Aw
// ---------------------------------------------------------------------------
__global__ __launch_bounds__(256) void attn_k(const float* __restrict__ Qp,
                                              const float* __restrict__ bq)
{
    int nh = blockIdx.x;
    int n = nh >> 4, h = nh & 15;
    int cbase = n * EM + h * HD;
    int hb = h * HD;

    __shared__ float sU[64][64];
    int tid = threadIdx.x;
    #pragma unroll
    for (int t = 0; t < 16; t++) {
        int idx = tid + t * 256;
        sU[idx >> 6][idx & 63] = g_vpr[nh * (HD * HD) + idx];
    }
    __syncthreads();

    int wid = tid >> 5, lane = tid & 31;
    float b0 = __ldg(&bq[hb + lane]);
    float b1 = __ldg(&bq[hb + lane + 32]);
    for (int lw = 0; lw < 16; lw++) {
        int l = blockIdx.y * 128 + wid * 16 + lw;
        size_t rb = (size_t)l * NCOLS + cbase;
        float q0 = Qp[rb + lane] + b0;
        float q1 = Qp[rb + lane + 32] + b1;
        float m = fmaxf(q0, q1);
        #pragma unroll
        for (int off = 16; off > 0; off >>= 1)
            m = fmaxf(m, __shfl_xor_sync(0xffffffffu, m, off));
        float e0 = __expf(q0 - m), e1 = __expf(q1 - m);
        float s = e0 + e1;
        #pragma unroll
        for (int off = 16; off > 0; off >>= 1)
            s += __shfl_xor_sync(0xffffffffu, s, off);
        float inv = 1.0f / s;
        e0 *= inv; e1 *= inv;
        float a0 = 0.0f, a1 = 0.0f;
        #pragma unroll
        for (int src = 0; src < 32; src++) {
            float p = __shfl_sync(0xffffffffu, e0, src);
            float qv = __shfl_sync(0xffffffffu, e1, src);
            a0 += p * sU[src][lane]      + qv * sU[src + 32][lane];
            a1 += p * sU[src][lane + 32] + qv * sU[src + 32][lane + 32];
        }
        size_t ob = ((size_t)l * NBATCH + n) * KSPLIT + h * HD;
        __nv_bfloat16 h0 = __float2bfloat16(a0);
        __nv_bfloat16 l0b = __float2bfloat16(a0 - __bfloat162float(h0));
        __nv_bfloat16 h1 = __float2bfloat16(a1);
        __nv_bfloat16 l1b = __float2bfloat16(a1 - __bfloat162float(h1));
        g_Aw[ob + lane] = h0;
        g_Aw[ob + lane + 32] = h1;
        g_Aw[ob + 1024 + lane] = l0b;
        g_Aw[ob + 1024 + lane + 32] = l1b;
    }
}

// ---------------------------------------------------------------------------
// Launch
// ---------------------------------------------------------------------------
extern "C" void kernel_launch(void* const* d_in, const int* in_sizes, int n_in,
                              void* d_out, int out_size)
{
    (void)in_sizes; (void)n_in; (void)out_size;
    const float* q  = (const float*)d_in[0];
    const float* k  = (const float*)d_in[1];
    const float* v  = (const float*)d_in[2];
    const float* Wq = (const float*)d_in[3];
    const float* bq = (const float*)d_in[4];
    const float* Wk = (const float*)d_in[5];
    const float* Wv = (const float*)d_in[7];
    const float* bv = (const float*)d_in[8];
    const float* Wo = (const float*)d_in[9];
    const float* bo = (const float*)d_in[10];
    float* out = (float*)d_out;

    void *pAw, *pWq, *pWk, *pWv, *pWo, *pQp, *pKp, *pVp;
    cudaGetSymbolAddress(&pAw, g_Aw);
    cudaGetSymbolAddress(&pWq, g_Wq);
    cudaGetSymbolAddress(&pWk, g_Wk);
    cudaGetSymbolAddress(&pWv, g_Wv);
    cudaGetSymbolAddress(&pWo, g_Wo);
    cudaGetSymbolAddress(&pQp, g_Qp);
    cudaGetSymbolAddress(&pKp, g_Kp);
    cudaGetSymbolAddress(&pVp, g_Vp);

    cudaFuncSetAttribute(gemm_bf16,
                         cudaFuncAttributeMaxDynamicSharedMemorySize, GEMM_SMEM);

    dim3 ggrid(EM / BN, MROWS / BM);   // (8, 128)
    const int ACT4 = MROWS * EM / 4;
    const int W4 = EM * EM / 4;
    const int TOT = MROWS * EM;

    // weight splits
    split_mat<<<512, 256>>>(Wq, (__nv_bfloat16*)pWq, W4);
    split_mat<<<512, 256>>>(Wk, (__nv_bfloat16*)pWk, W4);
    split_mat<<<512, 256>>>(Wv, (__nv_bfloat16*)pWv, W4);
    split_mat<<<512, 256>>>(Wo, (__nv_bfloat16*)pWo, W4);

    // projections (bias-free: bk cancels, bq/bv folded downstream)
    split_mat<<<4096, 256>>>(q, (__nv_bfloat16*)pAw, ACT4);
    gemm_bf16<<<ggrid, 256, GEMM_SMEM>>>((const __nv_bfloat16*)pAw,
                              (const __nv_bfloat16*)pWq, (float*)pQp);
    split_mat<<<4096, 256>>>(k, (__nv_bfloat16*)pAw, ACT4);
    gemm_bf16<<<ggrid, 256, GEMM_SMEM>>>((const __nv_bfloat16*)pAw,
                              (const __nv_bfloat16*)pWk, (float*)pKp);
    split_mat<<<4096, 256>>>(v, (__nv_bfloat16*)pAw, ACT4);
    gemm_bf16<<<ggrid, 256, GEMM_SMEM>>>((const __nv_bfloat16*)pAw,
                              (const __nv_bfloat16*)pWv, (float*)pVp);

    // column softmax stats over l for K
    init_stats<<<16, 256>>>();
    col_max_k<<<dim3(16, NROWBLK), 256>>>((const float*)pKp);
    col_sum_k<<<dim3(16, NROWBLK), 256>>>((const float*)pKp);
    sum_combine<<<16, 256>>>();

    // attention core
    vprime_k<<<dim3(NBATCH * NH, 8), 256>>>((const float*)pKp, (const float*)pVp);
    vpr_combine<<<NBATCH * NH, 256>>>(bv);
    attn_k<<<dim3(NBATCH * NH, 32), 256>>>((const float*)pQp, bq);

    // output projection (+bo)
    gemm_bf16<<<ggrid, 256, GEMM_SMEM>>>((const __nv_bfloat16*)pAw,
                              (const __nv_bfloat16*)pWo, out);
    add_bias<<<2048, 256>>>(out, bo, TOT);
}

// round 16
// speedup vs baseline: 2.5229x; 2.2743x over previous
#include <cuda_runtime.h>
#include <cuda_fp16.h>
#include <mma.h>
#include <cstdint>
using namespace nvcuda;

// ---------------------------------------------------------------------------
// Problem constants
// ---------------------------------------------------------------------------
#define LQ 4096
#define NBATCH 4
#define EM 1024
#define NH 16
#define HD 64
#define MROWS (LQ * NBATCH)        // 16384
#define NCOLS (NBATCH * EM)        // 4096 ([L, N*E] view)
#define NROWBLK 32

// ---------------------------------------------------------------------------
// Scratch (device globals; allocation is forbidden)
// ---------------------------------------------------------------------------
__device__ __half g_Aw[(size_t)MROWS * EM];     // fp16 activations (32MB)
__device__ __half g_Wq[(size_t)EM * EM];
__device__ __half g_Wk[(size_t)EM * EM];
__device__ __half g_Wv[(size_t)EM * EM];
__device__ __half g_Wo[(size_t)EM * EM];
__device__ float g_Qp[(size_t)MROWS * EM];
__device__ float g_Kp[(size_t)MROWS * EM];
__device__ float g_Vp[(size_t)MROWS * EM];
__device__ unsigned int g_cmax[NCOLS];
__device__ float g_csum[NCOLS];
__device__ float g_psum[NROWBLK * NCOLS];
__device__ float g_vpr8[8 * NBATCH * NH * HD * HD];       // L-split partials
__device__ float g_vpr[NBATCH * NH * HD * HD];            // [nh][d][e']

__device__ __forceinline__ uint32_t smem_to_u32(const void* p) {
    uint32_t a;
    asm("{ .reg .u64 t; cvta.to.shared.u64 t, %1; cvt.u32.u64 %0, t; }"
        : "=r"(a) : "l"(p));
    return a;
}

__device__ __forceinline__ void cp16(uint32_t sp, const void* gp) {
    asm volatile("cp.async.cg.shared.global [%0], [%1], 16;"
                 :: "r"(sp), "l"(gp));
}
#define CP_COMMIT() asm volatile("cp.async.commit_group;" ::: "memory")
#define CP_WAIT1()  asm volatile("cp.async.wait_group 1;" ::: "memory")

// ---------------------------------------------------------------------------
// Plain fp16 NT GEMM: C[M,1024] = A[M,1024] * B[1024,1024]^T, fp32 accum.
// Exact R10-proven structure: 128x128 CTA tile, BK=32, 2-stage cp.async
// double buffer, 8 warps (warp tile 32x64), occupancy 2.
// ---------------------------------------------------------------------------
#define BM 128
#define BN 128
#define BK 32
#define LDSM 40                    // fp16 leading dim (pad 32 -> 40)
#define GITER (EM / BK)            // 32

__global__ __launch_bounds__(256, 2) void gemm_fp16(
    const __half* __restrict__ A,
    const __half* __restrict__ B,
    float* __restrict__ C)
{
    __shared__ __half sA[2][BM * LDSM];
    __shared__ __half sB[2][BN * LDSM];

    int tid = threadIdx.x;
    int m0 = blockIdx.y * BM, n0 = blockIdx.x * BN;
    int wid = tid >> 5, wm = wid & 3, wn = wid >> 2;

    wmma::fragment<wmma::accumulator, 16, 16, 16, float> acc[2][4];
    #pragma unroll
    for (int i = 0; i < 2; i++)
        #pragma unroll
        for (int j = 0; j < 4; j++)
            wmma::fill_fragment(acc[i][j], 0.0f);

    const int lr = tid >> 2;             // 0..63
    const int lc = (tid & 3) * 8;        // 0,8,16,24 (fp16 elems; 16B chunks)

    #define LOAD_STAGE(s, k0) do { \
        cp16(smem_to_u32(&sA[s][lr * LDSM + lc]), \
             A + (size_t)(m0 + lr) * EM + (k0) + lc); \
        cp16(smem_to_u32(&sA[s][(lr + 64) * LDSM + lc]), \
             A + (size_t)(m0 + lr + 64) * EM + (k0) + lc); \
        cp16(smem_to_u32(&sB[s][lr * LDSM + lc]), \
             B + (size_t)(n0 + lr) * EM + (k0) + lc); \
        cp16(smem_to_u32(&sB[s][(lr + 64) * LDSM + lc]), \
             B + (size_t)(n0 + lr + 64) * EM + (k0) + lc); \
    } while (0)

    LOAD_STAGE(0, 0);
    CP_COMMIT();

    for (int it = 0; it < GITER; it++) {
        if (it + 1 < GITER)
            LOAD_STAGE((it + 1) & 1, (it + 1) * BK);
        CP_COMMIT();
        CP_WAIT1();          // newest (possibly empty) may pend; stage it ready
        __syncthreads();

        const __half* pa = sA[it & 1];
        const __half* pb = sB[it & 1];
        #pragma unroll
        for (int kk = 0; kk < BK; kk += 16) {
            wmma::fragment<wmma::matrix_a, 16, 16, 16, __half,
                           wmma::row_major> af[2];
            wmma::load_matrix_sync(af[0], pa + (wm * 32) * LDSM + kk, LDSM);
            wmma::load_matrix_sync(af[1], pa + (wm * 32 + 16) * LDSM + kk, LDSM);
            #pragma unroll
            for (int j = 0; j < 4; j++) {
                wmma::fragment<wmma::matrix_b, 16, 16, 16, __half,
                               wmma::col_major> bf;
                wmma::load_matrix_sync(bf,
                    pb + (wn * 64 + j * 16) * LDSM + kk, LDSM);
                wmma::mma_sync(acc[0][j], af[0], bf, acc[0][j]);
                wmma::mma_sync(acc[1][j], af[1], bf, acc[1][j]);
            }
        }
        __syncthreads();
    }

    #pragma unroll
    for (int i = 0; i < 2; i++)
        #pragma unroll
        for (int j = 0; j < 4; j++) {
            int row0 = m0 + wm * 32 + i * 16;
            int col0 = n0 + wn * 64 + j * 16;
            wmma::store_matrix_sync(C + (size_t)row0 * EM + col0, acc[i][j],
                                    EM, wmma::mem_row_major);
        }
    #undef LOAD_STAGE
}

// ---------------------------------------------------------------------------
// fp32 -> fp16 convert (contiguous)
// ---------------------------------------------------------------------------
__global__ void conv_mat(const float* __restrict__ src,
                         __half* __restrict__ dst, int total4)
{
    for (int i4 = blockIdx.x * blockDim.x + threadIdx.x; i4 < total4;
         i4 += gridDim.x * blockDim.x) {
        float4 f = ((const float4*)src)[i4];
        __half2 h01 = __floats2half2_rn(f.x, f.y);
        __half2 h23 = __floats2half2_rn(f.z, f.w);
        ((__half2*)dst)[i4 * 2]     = h01;
        ((__half2*)dst)[i4 * 2 + 1] = h23;
    }
}

// ---------------------------------------------------------------------------
// Bias add (final output only; bk cancels in softmax_l, bq/bv folded later)
// ---------------------------------------------------------------------------
__global__ void add_bias(float* __restrict__ C, const float* __restrict__ b,
                         int total)
{
    for (int i = blockIdx.x * blockDim.x + threadIdx.x; i < total;
         i += gridDim.x * blockDim.x)
        C[i] += __ldg(&b[i & (EM - 1)]);
}

// ---------------------------------------------------------------------------
// Column softmax stats (over l, per (n,e) column of Kp; bias-free — it cancels)
// ---------------------------------------------------------------------------
__device__ __forceinline__ unsigned int fenc(float f) {
    unsigned int u = __float_as_uint(f);
    return (u & 0x80000000u) ? ~u : (u | 0x80000000u);
}
__device__ __forceinline__ float fdec(unsigned int u) {
    return (u & 0x80000000u) ? __uint_as_float(u & 0x7fffffffu)
                             : __uint_as_float(~u);
}

__global__ void init_stats()
{
    int c = blockIdx.x * blockDim.x + threadIdx.x;
    if (c < NCOLS) g_cmax[c] = 0u;
}

__global__ void col_max_k(const float* __restrict__ Kp)
{
    int c = blockIdx.x * blockDim.x + threadIdx.x;
    int r0 = blockIdx.y * (LQ / NROWBLK);
    float m = -3.0e38f;
    #pragma unroll 4
    for (int r = 0; r < LQ / NROWBLK; r++)
        m = fmaxf(m, Kp[(size_t)(r0 + r) * NCOLS + c]);
    atomicMax(&g_cmax[c], fenc(m));
}

__global__ void col_sum_k(const float* __restrict__ Kp)
{
    int c = blockIdx.x * blockDim.x + threadIdx.x;
    int rb = blockIdx.y;
    int r0 = rb * (LQ / NROWBLK);
    float mx = fdec(g_cmax[c]);
    float s = 0.0f;
    #pragma unroll 4
    for (int r = 0; r < LQ / NROWBLK; r++)
        s += __expf(Kp[(size_t)(r0 + r) * NCOLS + c] - mx);
    g_psum[rb * NCOLS + c] = s;
}

__global__ void sum_combine()
{
    int c = blockIdx.x * blockDim.x + threadIdx.x;
    if (c >= NCOLS) return;
    float s = 0.0f;
    #pragma unroll
    for (int rb = 0; rb < NROWBLK; rb++) s += g_psum[rb * NCOLS + c];
    g_csum[c] = s;
}

// ---------------------------------------------------------------------------
// v' = softmax_l(K)^T @ V per (n,h); L split into 8 partials
// ---------------------------------------------------------------------------
__global__ __launch_bounds__(256) void vprime_k(const float* __restrict__ Kp,
                                                const float* __restrict__ Vp)
{
    int nh = blockIdx.x;
    int ls = blockIdx.y;                // 0..7
    int n = nh >> 4, h = nh & 15;
    int cbase = n * EM + h * HD;

    __shared__ float sK[32][64];
    __shared__ float sV[32][64];
    __shared__ float sMax[64], sInv[64];

    int tid = threadIdx.x;
    if (tid < 64) {
        sMax[tid] = fdec(g_cmax[cbase + tid]);
        sInv[tid] = 1.0f / g_csum[cbase + tid];
    }
    __syncthreads();

    float accv[16];
    #pragma unroll
    for (int i = 0; i < 16; i++) accv[i] = 0.0f;
    int tx = tid & 63;
    int ty = tid >> 6;

    int lbeg = ls * (LQ / 8), lend = lbeg + (LQ / 8);
    for (int l0 = lbeg; l0 < lend; l0 += 32) {
        #pragma unroll
        for (int t = 0; t < 8; t++) {
            int idx = tid + t * 256;
            int r = idx >> 6, cc = idx & 63;
            size_t g = (size_t)(l0 + r) * NCOLS + cbase + cc;
            float kv = Kp[g];
            sK[r][cc] = __expf(kv - sMax[cc]) * sInv[cc];
            sV[r][cc] = Vp[g];
        }
        __syncthreads();
        #pragma unroll 8
        for (int l = 0; l < 32; l++) {
            float vv = sV[l][tx];
            #pragma unroll
            for (int i = 0; i < 16; i++)
                accv[i] += sK[l][ty + i * 4] * vv;
        }
        __syncthreads();
    }
    #pragma unroll
    for (int i = 0; i < 16; i++)
        g_vpr8[((size_t)ls * 64 + nh) * (HD * HD) + (ty + i * 4) * HD + tx] = accv[i];
}

// combine partials; fold bv: v'[d][e'] += bv[h*HD + e'] (since sum_l softmax = 1)
__global__ void vpr_combine(const float* __restrict__ bv)
{
    int nh = blockIdx.x;
    int hb = (nh & 15) * HD;
    for (int idx = threadIdx.x; idx < HD * HD; idx += blockDim.x) {
        float s = 0.0f;
        #pragma unroll
        for (int ls = 0; ls < 8; ls++)
            s += g_vpr8[((size_t)ls * 64 + nh) * (HD * HD) + idx];
        g_vpr[nh * (HD * HD) + idx] = s + __ldg(&bv[hb + (idx & 63)]);
    }
}

// ---------------------------------------------------------------------------
// attn = softmax_d(Q + bq) @ v'; writes fp16 directly into g_Aw
// ---------------------------------------------------------------------------
__global__ __launch_bounds__(256) void attn_k(const float* __restrict__ Qp,
                                              const float* __restrict__ bq)
{
    int nh = blockIdx.x;
    int n = nh >> 4, h = nh & 15;
    int cbase = n * EM + h * HD;
    int hb = h * HD;

    __shared__ float sU[64][64];
    int tid = threadIdx.x;
    #pragma unroll
    for (int t = 0; t < 16; t++) {
        int idx = tid + t * 256;
        sU[idx >> 6][idx & 63] = g_vpr[nh * (HD * HD) + idx];
    }
    __syncthreads();

    int wid = tid >> 5, lane = tid & 31;
    float b0 = __ldg(&bq[hb + lane]);
    float b1 = __ldg(&bq[hb + lane + 32]);
    for (int lw = 0; lw < 16; lw++) {
        int l = blockIdx.y * 128 + wid * 16 + lw;
        size_t rb = (size_t)l * NCOLS + cbase;
        float q0 = Qp[rb + lane] + b0;
        float q1 = Qp[rb + lane + 32] + b1;
        float m = fmaxf(q0, q1);
        #pragma unroll
        for (int off = 16; off > 0; off >>= 1)
            m = fmaxf(m, __shfl_xor_sync(0xffffffffu, m, off));
        float e0 = __expf(q0 - m), e1 = __expf(q1 - m);
        float s = e0 + e1;
        #pragma unroll
        for (int off = 16; off > 0; off >>= 1)
            s += __shfl_xor_sync(0xffffffffu, s, off);
        float inv = 1.0f / s;
        e0 *= inv; e1 *= inv;
        float a0 = 0.0f, a1 = 0.0f;
        #pragma unroll
        for (int src = 0; src < 32; src++) {
            float p = __shfl_sync(0xffffffffu, e0, src);
            float qv = __shfl_sync(0xffffffffu, e1, src);
            a0 += p * sU[src][lane]      + qv * sU[src + 32][lane];
            a1 += p * sU[src][lane + 32] + qv * sU[src + 32][lane + 32];
        }
        size_t ob = ((size_t)l * NBATCH + n) * EM + h * HD;
        g_Aw[ob + lane]      = __float2half_rn(a0);
        g_Aw[ob + lane + 32] = __float2half_rn(a1);
    }
}

// ---------------------------------------------------------------------------
// Launch
// ---------------------------------------------------------------------------
extern "C" void kernel_launch(void* const* d_in, const int* in_sizes, int n_in,
                              void* d_out, int out_size)
{
    (void)in_sizes; (void)n_in; (void)out_size;
    const float* q  = (const float*)d_in[0];
    const float* k  = (const float*)d_in[1];
    const float* v  = (const float*)d_in[2];
    const float* Wq = (const float*)d_in[3];
    const float* bq = (const float*)d_in[4];
    const float* Wk = (const float*)d_in[5];
    const float* Wv = (const float*)d_in[7];
    const float* bv = (const float*)d_in[8];
    const float* Wo = (const float*)d_in[9];
    const float* bo = (const float*)d_in[10];
    float* out = (float*)d_out;

    void *pAw, *pWq, *pWk, *pWv, *pWo, *pQp, *pKp, *pVp;
    cudaGetSymbolAddress(&pAw, g_Aw);
    cudaGetSymbolAddress(&pWq, g_Wq);
    cudaGetSymbolAddress(&pWk, g_Wk);
    cudaGetSymbolAddress(&pWv, g_Wv);
    cudaGetSymbolAddress(&pWo, g_Wo);
    cudaGetSymbolAddress(&pQp, g_Qp);
    cudaGetSymbolAddress(&pKp, g_Kp);
    cudaGetSymbolAddress(&pVp, g_Vp);

    dim3 ggrid(EM / BN, MROWS / BM);   // (8, 128)
    const int ACT4 = MROWS * EM / 4;
    const int W4 = EM * EM / 4;
    const int TOT = MROWS * EM;

    // weight converts
    conv_mat<<<512, 256>>>(Wq, (__half*)pWq, W4);
    conv_mat<<<512, 256>>>(Wk, (__half*)pWk, W4);
    conv_mat<<<512, 256>>>(Wv, (__half*)pWv, W4);
    conv_mat<<<512, 256>>>(Wo, (__half*)pWo, W4);

    // projections (bias-free: bk cancels, bq/bv folded downstream)
    conv_mat<<<4096, 256>>>(q, (__half*)pAw, ACT4);
    gemm_fp16<<<ggrid, 256>>>((const __half*)pAw, (const __half*)pWq,
                              (float*)pQp);
    conv_mat<<<4096, 256>>>(k, (__half*)pAw, ACT4);
    gemm_fp16<<<ggrid, 256>>>((const __half*)pAw, (const __half*)pWk,
                              (float*)pKp);
    conv_mat<<<4096, 256>>>(v, (__half*)pAw, ACT4);
    gemm_fp16<<<ggrid, 256>>>((const __half*)pAw, (const __half*)pWv,
                              (float*)pVp);

    // column softmax stats over l for K
    init_stats<<<16, 256>>>();
    col_max_k<<<dim3(16, NROWBLK), 256>>>((const float*)pKp);
    col_sum_k<<<dim3(16, NROWBLK), 256>>>((const float*)pKp);
    sum_combine<<<16, 256>>>();

    // attention core
    vprime_k<<<dim3(NBATCH * NH, 8), 256>>>((const float*)pKp, (const float*)pVp);
    vpr_combine<<<NBATCH * NH, 256>>>(bv);
    attn_k<<<dim3(NBATCH * NH, 32), 256>>>((const float*)pQp, bq);

    // output projection (+bo); attn wrote fp16 A directly
    gemm_fp16<<<ggrid, 256>>>((const __half*)pAw, (const __half*)pWo, out);
    add_bias<<<2048, 256>>>(out, bo, TOT);
}